// round 9
// baseline (speedup 1.0000x reference)
#include <cuda_runtime.h>
#include <cuda_fp16.h>
#include <cuda_bf16.h>

#define D_IN   128
#define D_OUT  64
#define MAX_NODES 65536
#define MAX_EDGES 1048576
#define SEG    384           // nodes scanned per CSR block (128 thr * 3)

// Scratch (device globals; zero-initialized at module load).
// Invariants across calls/replays: g_cnt == 0 (aggregate resets),
// barrier counters self-reset (generation-based).
__device__ __half   g_h[(size_t)MAX_NODES * D_OUT];
__device__ int      g_cnt[MAX_NODES];
__device__ int      g_row_ptr[MAX_NODES];
__device__ int      g_fill_ptr[MAX_NODES];
__device__ int      g_adj[MAX_EDGES];
__device__ int      g_part[256];
__device__ unsigned g_bar_arrive[2];
__device__ unsigned g_bar_gen[2];

// ---------------------------------------------------------------------------
// Generation-based inter-block barrier (all participating blocks resident).
// id 0: CSR sub-group barrier; id 1: global barrier.
// ---------------------------------------------------------------------------
__device__ __forceinline__ void blocks_sync(int id, unsigned count) {
    __syncthreads();
    if (threadIdx.x == 0) {
        __threadfence();
        unsigned gen = atomicAdd(&g_bar_gen[id], 0u);
        unsigned old = atomicAdd(&g_bar_arrive[id], 1u);
        if (old == count - 1u) {
            g_bar_arrive[id] = 0u;
            __threadfence();
            atomicAdd(&g_bar_gen[id], 1u);
        } else {
            while (atomicAdd(&g_bar_gen[id], 0u) == gen) __nanosleep(64);
        }
        __threadfence();
    }
    __syncthreads();
}

// ---------------------------------------------------------------------------
// f32x2 packed helpers
// ---------------------------------------------------------------------------
__device__ __forceinline__ unsigned long long pk2(float a, float b) {
    unsigned long long r;
    asm("mov.b64 %0, {%1, %2};" : "=l"(r) : "f"(a), "f"(b));
    return r;
}
__device__ __forceinline__ void ffma2(unsigned long long& d,
                                      unsigned long long a,
                                      unsigned long long b) {
    asm("fma.rn.f32x2 %0, %1, %2, %3;" : "=l"(d) : "l"(a), "l"(b), "l"(d));
}
__device__ __forceinline__ float2 upk2(unsigned long long v) {
    float2 f;
    asm("mov.b64 {%0, %1}, %2;" : "=f"(f.x), "=f"(f.y) : "l"(v));
    return f;
}

// ---------------------------------------------------------------------------
// The single fused kernel. 128 threads/block, grid = 2 * SM count.
// Blocks [0, gemmb): GEMM tiles.  Blocks [gemmb, nblocks): CSR build.
// Then global barrier, then all blocks aggregate.
// ---------------------------------------------------------------------------
extern __shared__ float4 dynsmem[];   // 2 * 64 * 33 float4 = 67584 B

__global__ void __launch_bounds__(128, 2) fused_kernel(
    const float* __restrict__ x, const float* __restrict__ W,
    const float* __restrict__ b, const int* __restrict__ row,
    const int* __restrict__ col, float* __restrict__ out,
    int N, int E, int nblocks, int gemmb)
{
    const int bid = blockIdx.x;
    const int tid = threadIdx.x;
    const int lane = tid & 31;
    const int w = tid >> 5;
    const int csrb = nblocks - gemmb;
    const int ntiles = (N + 63) / 64;

    if (bid < gemmb) {
        // =================== GEMM side ===================
        float4* xs = dynsmem;               // [64][33]
        float4* ws = dynsmem + 64 * 33;     // [64][33]
        const float4* W4 = (const float4*)W;
        const float4* x4 = (const float4*)x;

        const int tx = tid & 15;
        const int ty = tid >> 4;

        for (int tile = bid; tile < ntiles; tile += gemmb) {
            const int nb = tile * 64;
#pragma unroll
            for (int i = 0; i < 16; i++) {
                int lin = tid + 128 * i;
                int r = lin >> 5, c = lin & 31;
                ws[r * 33 + c] = W4[lin];
                int node = nb + r;
                float4 v = make_float4(0.f, 0.f, 0.f, 0.f);
                if (node < N) v = x4[node * 32 + c];
                xs[r * 33 + c] = v;
            }
            __syncthreads();

            unsigned long long acc[8][4];
#pragma unroll
            for (int i = 0; i < 8; i++)
#pragma unroll
                for (int j = 0; j < 4; j++) acc[i][j] = 0ull;

#pragma unroll 4
            for (int k = 0; k < 32; k++) {
                unsigned long long xlo[8], xhi[8], wlo[4], whi[4];
#pragma unroll
                for (int i = 0; i < 8; i++) {
                    float4 v = xs[(ty + 8 * i) * 33 + k];
                    xlo[i] = pk2(v.x, v.y);
                    xhi[i] = pk2(v.z, v.w);
                }
#pragma unroll
                for (int j = 0; j < 4; j++) {
                    float4 v = ws[(tx + 16 * j) * 33 + k];
                    wlo[j] = pk2(v.x, v.y);
                    whi[j] = pk2(v.z, v.w);
                }
#pragma unroll
                for (int i = 0; i < 8; i++)
#pragma unroll
                    for (int j = 0; j < 4; j++) {
                        ffma2(acc[i][j], xlo[i], wlo[j]);
                        ffma2(acc[i][j], xhi[i], whi[j]);
                    }
            }

            float bias[4];
#pragma unroll
            for (int j = 0; j < 4; j++) bias[j] = __ldg(&b[tx + 16 * j]);

#pragma unroll
            for (int i = 0; i < 8; i++) {
                int node = nb + ty + 8 * i;
                if (node < N) {
#pragma unroll
                    for (int j = 0; j < 4; j++) {
                        float2 p = upk2(acc[i][j]);
                        g_h[(size_t)node * D_OUT + tx + 16 * j] =
                            __float2half(p.x + p.y + bias[j]);
                    }
                }
            }
            __syncthreads();   // smem reuse safety for next tile
        }
    } else {
        // =================== CSR side ===================
        const int cb = bid - gemmb;            // 0..csrb-1
        const int cstride = csrb * 128;

        // ---- Phase 1: in-degree histogram (relies on g_cnt == 0) ----
        for (int e = cb * 128 + tid; e < E; e += cstride)
            atomicAdd(&g_cnt[__ldg(&row[e])], 1);
        blocks_sync(0, csrb);

        // ---- Phase 2a: block-local scan over SEG nodes, emit partial ----
        __shared__ int wsum[4];
        const int base_i = cb * SEG + tid * 3;     // < csrb*SEG <= 58368 < MAX_NODES
        int v0 = g_cnt[base_i];
        int v1 = g_cnt[base_i + 1];
        int v2 = g_cnt[base_i + 2];
        int tsum = v0 + v1 + v2;

        int inc = tsum;
#pragma unroll
        for (int off = 1; off < 32; off <<= 1) {
            int t = __shfl_up_sync(~0u, inc, off);
            if (lane >= off) inc += t;
        }
        if (lane == 31) wsum[w] = inc;
        __syncthreads();
        int wpre = 0;
#pragma unroll
        for (int i = 0; i < 4; i++) wpre += (i < w) ? wsum[i] : 0;
        int excl = wpre + inc - tsum;              // exclusive prefix within block
        if (tid == 0) g_part[cb] = wsum[0] + wsum[1] + wsum[2] + wsum[3];
        blocks_sync(0, csrb);

        // ---- Phase 2b: single warp scans the csrb partials (exclusive) ----
        if (cb == 0 && w == 0) {
            int vals[5];
            int gsum = 0;
#pragma unroll
            for (int k = 0; k < 5; k++) {
                int idx = lane * 5 + k;
                vals[k] = (idx < csrb) ? g_part[idx] : 0;
                gsum += vals[k];
            }
            int ginc = gsum;
#pragma unroll
            for (int off = 1; off < 32; off <<= 1) {
                int t = __shfl_up_sync(~0u, ginc, off);
                if (lane >= off) ginc += t;
            }
            int pre = ginc - gsum;
#pragma unroll
            for (int k = 0; k < 5; k++) {
                int idx = lane * 5 + k;
                if (idx < csrb) g_part[idx] = pre;
                pre += vals[k];
            }
        }
        blocks_sync(0, csrb);

        // ---- Phase 2c: write row_ptr / fill_ptr ----
        {
            int e0 = g_part[cb] + excl;
            g_row_ptr[base_i]      = e0;
            g_fill_ptr[base_i]     = e0;
            e0 += v0;
            g_row_ptr[base_i + 1]  = e0;
            g_fill_ptr[base_i + 1] = e0;
            e0 += v1;
            g_row_ptr[base_i + 2]  = e0;
            g_fill_ptr[base_i + 2] = e0;
        }
        blocks_sync(0, csrb);

        // ---- Phase 3: fill adjacency ----
        for (int e = cb * 128 + tid; e < E; e += cstride) {
            int r = __ldg(&row[e]);
            int pos = atomicAdd(&g_fill_ptr[r], 1);
            g_adj[pos] = __ldg(&col[e]);
        }
    }

    // =================== Join, then aggregate on all blocks ===================
    blocks_sync(1, (unsigned)nblocks);

    const int nwarps = nblocks * 4;
    const __half2* h2 = (const __half2*)g_h;

    for (int node = bid * 4 + w; node < N; node += nwarps) {
        int start = __ldg(&g_row_ptr[node]);
        int deg   = __ldg(&g_cnt[node]);
        if (lane == 0) g_cnt[node] = 0;        // restore invariant for replay

        float2 acc = make_float2(0.f, 0.f);
        int j = 0;
        for (; j + 8 <= deg; j += 8) {
            int c0 = __ldg(&g_adj[start + j]);
            int c1 = __ldg(&g_adj[start + j + 1]);
            int c2 = __ldg(&g_adj[start + j + 2]);
            int c3 = __ldg(&g_adj[start + j + 3]);
            int c4 = __ldg(&g_adj[start + j + 4]);
            int c5 = __ldg(&g_adj[start + j + 5]);
            int c6 = __ldg(&g_adj[start + j + 6]);
            int c7 = __ldg(&g_adj[start + j + 7]);
            float2 f0 = __half22float2(h2[c0 * 32 + lane]);
            float2 f1 = __half22float2(h2[c1 * 32 + lane]);
            float2 f2 = __half22float2(h2[c2 * 32 + lane]);
            float2 f3 = __half22float2(h2[c3 * 32 + lane]);
            float2 f4 = __half22float2(h2[c4 * 32 + lane]);
            float2 f5 = __half22float2(h2[c5 * 32 + lane]);
            float2 f6 = __half22float2(h2[c6 * 32 + lane]);
            float2 f7 = __half22float2(h2[c7 * 32 + lane]);
            acc.x += ((f0.x + f1.x) + (f2.x + f3.x)) + ((f4.x + f5.x) + (f6.x + f7.x));
            acc.y += ((f0.y + f1.y) + (f2.y + f3.y)) + ((f4.y + f5.y) + (f6.y + f7.y));
        }
        for (; j < deg; j++) {
            int c = __ldg(&g_adj[start + j]);
            float2 f = __half22float2(h2[c * 32 + lane]);
            acc.x += f.x; acc.y += f.y;
        }

        float d = fmaxf((float)deg, 1.0f);
        acc.x /= d; acc.y /= d;
        ((float2*)out)[node * 32 + lane] = acc;
    }
}

// ---------------------------------------------------------------------------
extern "C" void kernel_launch(void* const* d_in, const int* in_sizes, int n_in,
                              void* d_out, int out_size)
{
    const float* x   = (const float*)d_in[0];
    const float* W   = (const float*)d_in[1];
    const float* b   = (const float*)d_in[2];
    const int*   row = (const int*)d_in[3];
    const int*   col = (const int*)d_in[4];
    float* out = (float*)d_out;

    int N = in_sizes[0] / D_IN;   // 50000
    int E = in_sizes[3];          // 800000

    static int nblocks = 0;
    if (nblocks == 0) {
        int dev = 0, sm = 148;
        cudaGetDevice(&dev);
        cudaDeviceGetAttribute(&sm, cudaDevAttrMultiProcessorCount, dev);
        nblocks = 2 * sm;
        cudaFuncSetAttribute(fused_kernel,
                             cudaFuncAttributeMaxDynamicSharedMemorySize, 69632);
    }
    int gemmb = nblocks / 2;

    fused_kernel<<<nblocks, 128, 67584>>>(x, W, b, row, col, out,
                                          N, E, nblocks, gemmb);
}

// round 10
// speedup vs baseline: 3.2097x; 3.2097x over previous
#include <cuda_runtime.h>
#include <cuda_fp16.h>
#include <cuda_bf16.h>

#define D_IN   128
#define D_OUT  64
#define MAX_NODES 50048
#define MAX_EDGES 1048576

// Scratch (device globals; zero-initialized at module load).
// Invariant across calls/replays: g_head == 0 (aggregate resets after use).
__device__ __half g_h[(size_t)MAX_NODES * D_OUT];   // fp16 projected features
__device__ int    g_head[MAX_NODES];                // 0 = empty, else edge_id+1
__device__ int2   g_list[MAX_EDGES];                // {next_ptr, col}

// ---------------------------------------------------------------------------
// f32x2 packed helpers
// ---------------------------------------------------------------------------
__device__ __forceinline__ unsigned long long pk2(float a, float b) {
    unsigned long long r;
    asm("mov.b64 %0, {%1, %2};" : "=l"(r) : "f"(a), "f"(b));
    return r;
}
__device__ __forceinline__ void ffma2(unsigned long long& d,
                                      unsigned long long a,
                                      unsigned long long b) {
    asm("fma.rn.f32x2 %0, %1, %2, %3;" : "=l"(d) : "l"(a), "l"(b), "l"(d));
}
__device__ __forceinline__ float2 upk2(unsigned long long v) {
    float2 f;
    asm("mov.b64 {%0, %1}, %2;" : "=f"(f.x), "=f"(f.y) : "l"(v));
    return f;
}

// ---------------------------------------------------------------------------
// K1: linked-list bucket build. One pass, no histogram, no scan.
// head[r] <- e+1 (atomicExch), list[e] = {old_head, col[e]} (coalesced 8B).
// Relies on g_head == 0 at entry.
// ---------------------------------------------------------------------------
__global__ void __launch_bounds__(256) build_kernel(const int* __restrict__ row,
                                                    const int* __restrict__ col, int E)
{
    int e = blockIdx.x * blockDim.x + threadIdx.x;
    if (e >= E) return;
    int r = __ldg(&row[e]);
    int c = __ldg(&col[e]);
    int old = atomicExch(&g_head[r], e + 1);
    g_list[e] = make_int2(old, c);
}

// ---------------------------------------------------------------------------
// K2: GEMM h = x @ W^T + b (f32x2 packed FMA), stores fp16.
// 128 threads, 64 nodes x 64 outs per block, thread tile 8x4.
// ---------------------------------------------------------------------------
__global__ void __launch_bounds__(128) gemm_kernel(
    const float* __restrict__ x, const float* __restrict__ W,
    const float* __restrict__ b, int N)
{
    __shared__ float4 xs[64][33];
    __shared__ float4 ws[64][33];

    const int tid = threadIdx.x;
    const int nb  = blockIdx.x * 64;

    const float4* W4 = (const float4*)W;
#pragma unroll
    for (int i = 0; i < 16; i++) {
        int lin = tid + 128 * i;
        int r = lin >> 5, c = lin & 31;
        ws[r][c] = W4[lin];
    }
    const float4* x4 = (const float4*)x;
#pragma unroll
    for (int i = 0; i < 16; i++) {
        int lin = tid + 128 * i;
        int r = lin >> 5, c = lin & 31;
        int node = nb + r;
        float4 v = make_float4(0.f, 0.f, 0.f, 0.f);
        if (node < N) v = x4[node * 32 + c];
        xs[r][c] = v;
    }
    __syncthreads();

    const int tx = tid & 15;
    const int ty = tid >> 4;

    unsigned long long acc[8][4];
#pragma unroll
    for (int i = 0; i < 8; i++)
#pragma unroll
        for (int j = 0; j < 4; j++) acc[i][j] = 0ull;

#pragma unroll 4
    for (int k = 0; k < 32; k++) {
        unsigned long long xlo[8], xhi[8], wlo[4], whi[4];
#pragma unroll
        for (int i = 0; i < 8; i++) {
            float4 v = xs[ty + 8 * i][k];
            xlo[i] = pk2(v.x, v.y);
            xhi[i] = pk2(v.z, v.w);
        }
#pragma unroll
        for (int j = 0; j < 4; j++) {
            float4 v = ws[tx + 16 * j][k];
            wlo[j] = pk2(v.x, v.y);
            whi[j] = pk2(v.z, v.w);
        }
#pragma unroll
        for (int i = 0; i < 8; i++) {
#pragma unroll
            for (int j = 0; j < 4; j++) {
                ffma2(acc[i][j], xlo[i], wlo[j]);
                ffma2(acc[i][j], xhi[i], whi[j]);
            }
        }
    }

    float bias[4];
#pragma unroll
    for (int j = 0; j < 4; j++) bias[j] = __ldg(&b[tx + 16 * j]);

#pragma unroll
    for (int i = 0; i < 8; i++) {
        int node = nb + ty + 8 * i;
        if (node < N) {
#pragma unroll
            for (int j = 0; j < 4; j++) {
                float2 p = upk2(acc[i][j]);
                g_h[(size_t)node * D_OUT + tx + 16 * j] =
                    __float2half(p.x + p.y + bias[j]);
            }
        }
    }
}

// ---------------------------------------------------------------------------
// K3: aggregate via list chase + normalize + write + reset head.
// One warp per node. Lane 0 chases (software-pipelined: next-chase load is
// issued before the gather's FADD consumes), all 32 lanes gather one 128B
// fp16 line per edge. deg counted during traversal.
// ---------------------------------------------------------------------------
__global__ void __launch_bounds__(256) aggregate_kernel(float* __restrict__ out, int N)
{
    int node = (blockIdx.x * blockDim.x + threadIdx.x) >> 5;
    int lane = threadIdx.x & 31;
    if (node >= N) return;

    int ptr = __ldg(&g_head[node]);
    if (lane == 0 && ptr != 0) g_head[node] = 0;   // restore invariant

    const __half2* h2 = (const __half2*)g_h;
    float2 acc = make_float2(0.f, 0.f);
    int deg = 0;

    // prime the pipeline: lane 0 loads the first list node
    int2 cur = make_int2(0, 0);
    if (lane == 0 && ptr != 0) cur = __ldg(&g_list[ptr - 1]);

    while (ptr != 0) {
        int nptr = __shfl_sync(~0u, cur.x, 0);
        int colv = __shfl_sync(~0u, cur.y, 0);

        // issue next chase load before consuming this gather
        int2 nxt = make_int2(0, 0);
        if (lane == 0 && nptr != 0) nxt = __ldg(&g_list[nptr - 1]);

        float2 f = __half22float2(h2[colv * 32 + lane]);
        acc.x += f.x;
        acc.y += f.y;
        deg++;

        ptr = nptr;
        cur = nxt;
    }

    float d = fmaxf((float)deg, 1.0f);
    acc.x /= d; acc.y /= d;
    ((float2*)out)[node * 32 + lane] = acc;
}

// ---------------------------------------------------------------------------
extern "C" void kernel_launch(void* const* d_in, const int* in_sizes, int n_in,
                              void* d_out, int out_size)
{
    const float* x   = (const float*)d_in[0];
    const float* W   = (const float*)d_in[1];
    const float* b   = (const float*)d_in[2];
    const int*   row = (const int*)d_in[3];
    const int*   col = (const int*)d_in[4];
    float* out = (float*)d_out;

    int N = in_sizes[0] / D_IN;   // 50000
    int E = in_sizes[3];          // 800000

    build_kernel<<<(E + 255) / 256, 256>>>(row, col, E);
    gemm_kernel<<<(N + 63) / 64, 128>>>(x, W, b, N);

    long long total = (long long)N * 32;
    aggregate_kernel<<<(int)((total + 255) / 256), 256>>>(out, N);
}